// round 7
// baseline (speedup 1.0000x reference)
#include <cuda_runtime.h>
#include <cuda_bf16.h>
#include <math.h>
#include <stdint.h>

// ---------------- problem constants ----------------
#define OHW         254
#define STRIP_OROWS 16
#define STRIPS      16
#define OCHUNKS     32          // output pixel chunks of 128 per strip
#define ICHUNKS     36          // + 4 halo chunks
#define NSLOTS      6
#define APITCH      112         // bytes per A/B row (96 data + 16 pad; conflict-free)
#define SLOT_BYTES  (128 * APITCH)       // 14336
#define BKH_BYTES   (64 * APITCH)        // 7168 per kh
#define OFF_BIAS    0                    // 64 floats
#define OFF_B       256
#define OFF_A       (OFF_B + 3 * BKH_BYTES)          // 21760
#define SMEM_BYTES  (OFF_A + NSLOTS * SLOT_BYTES)    // 107776  (x2 CTAs = 215552)

__device__ __forceinline__ uint32_t smem_u32(const void* p) {
    uint32_t a;
    asm("{ .reg .u64 t; cvta.to.shared.u64 t, %1; cvt.u32.u64 %0, t; }"
        : "=r"(a) : "l"(p));
    return a;
}
__device__ __forceinline__ void ldmatrix_x4(uint32_t& a0, uint32_t& a1,
                                            uint32_t& a2, uint32_t& a3,
                                            uint32_t addr) {
    asm volatile("ldmatrix.sync.aligned.m8n8.x4.shared.b16 {%0,%1,%2,%3}, [%4];"
                 : "=r"(a0), "=r"(a1), "=r"(a2), "=r"(a3) : "r"(addr));
}
__device__ __forceinline__ void mma_bf16(float* c, uint32_t a0, uint32_t a1,
                                         uint32_t a2, uint32_t a3,
                                         uint32_t b0, uint32_t b1) {
    asm volatile(
        "mma.sync.aligned.m16n8k16.row.col.f32.bf16.bf16.f32 "
        "{%0,%1,%2,%3}, {%4,%5,%6,%7}, {%8,%9}, {%0,%1,%2,%3};"
        : "+f"(c[0]), "+f"(c[1]), "+f"(c[2]), "+f"(c[3])
        : "r"(a0), "r"(a1), "r"(a2), "r"(a3), "r"(b0), "r"(b1));
}
__device__ __forceinline__ uint32_t pkbf(float lo, float hi) {
    __nv_bfloat162 t = __float22bfloat162_rn(make_float2(lo, hi));
    return *reinterpret_cast<uint32_t*>(&t);
}

extern __shared__ char smem[];

// Load the 24 input values for one A row of chunk ch (2 threads/row, half h).
__device__ __forceinline__ void load_vals(int ch, int oy0,
                                          const float* __restrict__ xb,
                                          int tid, float* v) {
    const int r  = tid & 127;
    const int h  = tid >> 7;
    const int p  = ch * 128 + r;
    const int iy = oy0 + (p >> 8);
    const int ix = p & 255;
    if (iy < 256) {
        const float* xp = xb + ((size_t)(h * 8) << 16) + iy * 256 + ix;
        #pragma unroll
        for (int c8 = 0; c8 < 8; c8++)
            #pragma unroll
            for (int kw = 0; kw < 3; kw++)
                v[c8 * 3 + kw] = (ix + kw < 256) ? __ldg(xp + (c8 << 16) + kw) : 0.0f;
    } else {
        #pragma unroll
        for (int e = 0; e < 24; e++) v[e] = 0.0f;
    }
}
// Convert + store the staged row into the ring slot.
__device__ __forceinline__ void store_vals(int ch, int tid, const float* v) {
    const int r = tid & 127;
    const int h = tid >> 7;
    uint32_t u[12];
    #pragma unroll
    for (int j = 0; j < 12; j++) u[j] = pkbf(v[2 * j], v[2 * j + 1]);
    char* base = smem + OFF_A + (ch % NSLOTS) * SLOT_BYTES + r * APITCH + h * 48;
    *reinterpret_cast<uint4*>(base)      = make_uint4(u[0], u[1], u[2],  u[3]);
    *reinterpret_cast<uint4*>(base + 16) = make_uint4(u[4], u[5], u[6],  u[7]);
    *reinterpret_cast<uint4*>(base + 32) = make_uint4(u[8], u[9], u[10], u[11]);
}

__global__ __launch_bounds__(256, 2)
void conv_mma_kernel(const float* __restrict__ x, const float* __restrict__ w,
                     const float* __restrict__ bias, float* __restrict__ out)
{
    const int tid  = threadIdx.x;
    const int warp = tid >> 5;
    const int lane = tid & 31;
    const int g    = lane >> 2;
    const int q    = lane & 3;

    const int strip = blockIdx.x;
    const int b     = blockIdx.y;
    const int oy0   = strip * STRIP_OROWS;
    const uint32_t sbase = smem_u32(smem);
    float* s_bias = (float*)(smem + OFF_BIAS);

    if (tid < 64) s_bias[tid] = __ldg(bias + tid);

    // ---- B into smem, once: rows = cout n (K-major, 48 bf16, per-kh block) ----
    for (int idx = tid; idx < 3 * 64 * 48; idx += 256) {
        const int kh = idx / (64 * 48);
        const int rm = idx % (64 * 48);
        const int n  = rm / 48;
        const int k  = rm % 48;
        const float val = __ldg(w + n * 144 + (k / 3) * 9 + kh * 3 + (k % 3));
        *reinterpret_cast<__nv_bfloat16*>(smem + OFF_B + kh * BKH_BYTES
                                          + n * APITCH + k * 2) = __float2bfloat16(val);
    }

    const float* xb = x + ((size_t)b << 20);

    // ---- prologue: chunks 0..4 ----
    #pragma unroll 1
    for (int pc = 0; pc < 5; pc++) {
        float v[24];
        load_vals(pc, oy0, xb, tid, v);
        store_vals(pc, tid, v);
    }
    __syncthreads();

    // A: warp tile M=16 rows [warp*16, warp*16+16), all 64 couts
    const uint32_t a_off = (uint32_t)((warp * 16 + (lane & 15)) * APITCH
                                      + ((lane >> 4) << 4));
    // B: load j covers n-tiles {2j,2j+1}: n = (2j + ((lane>>3)>>1))*8 + (lane&7)
    const uint32_t b_off = (uint32_t)(((((lane >> 3) >> 1) * 8) + (lane & 7)) * APITCH
                                      + (((lane >> 3) & 1) << 4));

    // ---- main pipeline (one __syncthreads per iteration) ----
    #pragma unroll 1
    for (int i = 0; i < OCHUNKS; i++) {
        // stage next build's loads early (latency hidden behind MMAs)
        const int ch = i + 5;
        float v[24];
        if (ch < ICHUNKS) load_vals(ch, oy0, xb, tid, v);

        float acc[8][4];
        #pragma unroll
        for (int nt = 0; nt < 8; nt++) {
            float lo = s_bias[nt * 8 + 2 * q];
            float hi = s_bias[nt * 8 + 2 * q + 1];
            acc[nt][0] = lo; acc[nt][1] = hi;
            acc[nt][2] = lo; acc[nt][3] = hi;
        }

        #pragma unroll
        for (int kh = 0; kh < 3; kh++) {
            const uint32_t slotbase = sbase + OFF_A
                                    + (uint32_t)(((i + 2 * kh) % NSLOTS) * SLOT_BYTES);
            const uint32_t bbase = sbase + OFF_B + kh * BKH_BYTES + b_off;
            #pragma unroll
            for (int s = 0; s < 3; s++) {
                uint32_t bf[16];
                #pragma unroll
                for (int j = 0; j < 4; j++)
                    ldmatrix_x4(bf[4 * j], bf[4 * j + 1], bf[4 * j + 2], bf[4 * j + 3],
                                bbase + (uint32_t)(j * 16 * APITCH) + s * 32);
                uint32_t a0, a1, a2, a3;
                ldmatrix_x4(a0, a1, a2, a3, slotbase + a_off + s * 32);
                #pragma unroll
                for (int nt = 0; nt < 8; nt++)
                    mma_bf16(acc[nt], a0, a1, a2, a3, bf[2 * nt], bf[2 * nt + 1]);
            }
        }

        // ---- warp-local epilogue: min over 64 couts -> tanh(tanh) -> store ----
        float m0 = fminf(acc[0][0], acc[0][1]);
        float m1 = fminf(acc[0][2], acc[0][3]);
        #pragma unroll
        for (int nt = 1; nt < 8; nt++) {
            m0 = fminf(m0, fminf(acc[nt][0], acc[nt][1]));
            m1 = fminf(m1, fminf(acc[nt][2], acc[nt][3]));
        }
        m0 = fminf(m0, __shfl_xor_sync(0xFFFFFFFFu, m0, 1));
        m0 = fminf(m0, __shfl_xor_sync(0xFFFFFFFFu, m0, 2));
        m1 = fminf(m1, __shfl_xor_sync(0xFFFFFFFFu, m1, 1));
        m1 = fminf(m1, __shfl_xor_sync(0xFFFFFFFFu, m1, 2));
        if (q == 0) {
            const int p0 = i * 128 + warp * 16 + g;   // row g; row g+8 = p0+8
            const int oy = oy0 + (p0 >> 8);           // p0, p0+8 share iy (g<8)
            const int ox = p0 & 255;
            if (oy < OHW) {
                float* op = out + ((size_t)b * OHW + oy) * OHW;
                if (ox < OHW)     op[ox]     = tanhf(tanhf(m0));
                if (ox + 8 < OHW) op[ox + 8] = tanhf(tanhf(m1));
            }
        }

        // commit staged build, then the single barrier
        if (ch < ICHUNKS) store_vals(ch, tid, v);
        __syncthreads();
    }
}

extern "C" void kernel_launch(void* const* d_in, const int* in_sizes, int n_in,
                              void* d_out, int out_size)
{
    const float* x    = (const float*)d_in[0];   // [64,16,256,256]
    const float* w    = (const float*)d_in[1];   // [64,16,3,3]
    const float* bias = (const float*)d_in[2];   // [64]
    float* out = (float*)d_out;                  // [64,1,254,254]

    cudaFuncSetAttribute(conv_mma_kernel,
                         cudaFuncAttributeMaxDynamicSharedMemorySize, SMEM_BYTES);

    dim3 grid(STRIPS, 64);   // 16 strips x 64 images = 1024 CTAs
    conv_mma_kernel<<<grid, 256, SMEM_BYTES>>>(x, w, bias, out);
}

// round 9
// speedup vs baseline: 1.2241x; 1.2241x over previous
#include <cuda_runtime.h>
#include <cuda_bf16.h>
#include <math.h>
#include <stdint.h>

// ---------------- problem constants ----------------
#define OHW         254
#define STRIP_OROWS 16
#define STRIPS      16
#define OCHUNKS     32          // output pixel chunks of 128 per strip
#define ICHUNKS     36          // buildable input chunks (rows oy0..oy0+17)
#define NSLOTS      6
#define APITCH      112         // bytes per A/B row (96 data + 16 pad; conflict-free)
#define SLOT_BYTES  (128 * APITCH)       // 14336
#define BKH_BYTES   (64 * APITCH)        // 7168 per kh
#define OFF_RED     0                    // 2 x 256 floats (ping-pong)
#define OFF_B       2048                 // 3 * 7168 = 21504
#define OFF_A       (OFF_B + 3 * BKH_BYTES)          // 23552
#define SMEM_BYTES  (OFF_A + NSLOTS * SLOT_BYTES)    // 109568  (x2 CTAs = 219136)

__device__ __forceinline__ uint32_t smem_u32(const void* p) {
    uint32_t a;
    asm("{ .reg .u64 t; cvta.to.shared.u64 t, %1; cvt.u32.u64 %0, t; }"
        : "=r"(a) : "l"(p));
    return a;
}
__device__ __forceinline__ void ldmatrix_x4(uint32_t& a0, uint32_t& a1,
                                            uint32_t& a2, uint32_t& a3,
                                            uint32_t addr) {
    asm volatile("ldmatrix.sync.aligned.m8n8.x4.shared.b16 {%0,%1,%2,%3}, [%4];"
                 : "=r"(a0), "=r"(a1), "=r"(a2), "=r"(a3) : "r"(addr));
}
__device__ __forceinline__ void mma_bf16(float* c, uint32_t a0, uint32_t a1,
                                         uint32_t a2, uint32_t a3,
                                         uint32_t b0, uint32_t b1) {
    asm volatile(
        "mma.sync.aligned.m16n8k16.row.col.f32.bf16.bf16.f32 "
        "{%0,%1,%2,%3}, {%4,%5,%6,%7}, {%8,%9}, {%0,%1,%2,%3};"
        : "+f"(c[0]), "+f"(c[1]), "+f"(c[2]), "+f"(c[3])
        : "r"(a0), "r"(a1), "r"(a2), "r"(a3), "r"(b0), "r"(b1));
}
__device__ __forceinline__ uint32_t pkbf(float lo, float hi) {
    __nv_bfloat162 t = __float22bfloat162_rn(make_float2(lo, hi));
    return *reinterpret_cast<uint32_t*>(&t);
}

extern __shared__ char smem[];

// Load the 24 input values for one A row of chunk ch (2 threads/row, half h).
__device__ __forceinline__ void load_vals(int ch, int oy0,
                                          const float* __restrict__ xb,
                                          int tid, float* v) {
    const int r  = tid & 127;
    const int h  = tid >> 7;
    const int p  = ch * 128 + r;
    const int iy = oy0 + (p >> 8);
    const int ix = p & 255;
    if (iy < 256) {
        const float* xp = xb + ((size_t)(h * 8) << 16) + iy * 256 + ix;
        #pragma unroll
        for (int c8 = 0; c8 < 8; c8++)
            #pragma unroll
            for (int kw = 0; kw < 3; kw++)
                v[c8 * 3 + kw] = (ix + kw < 256) ? __ldg(xp + (c8 << 16) + kw) : 0.0f;
    } else {
        #pragma unroll
        for (int e = 0; e < 24; e++) v[e] = 0.0f;
    }
}
// Convert + store one staged row into the ring slot.
__device__ __forceinline__ void store_vals(int ch, int tid, const float* v) {
    const int r = tid & 127;
    const int h = tid >> 7;
    uint32_t u[12];
    #pragma unroll
    for (int j = 0; j < 12; j++) u[j] = pkbf(v[2 * j], v[2 * j + 1]);
    char* base = smem + OFF_A + (ch % NSLOTS) * SLOT_BYTES + r * APITCH + h * 48;
    *reinterpret_cast<uint4*>(base)      = make_uint4(u[0], u[1], u[2],  u[3]);
    *reinterpret_cast<uint4*>(base + 16) = make_uint4(u[4], u[5], u[6],  u[7]);
    *reinterpret_cast<uint4*>(base + 32) = make_uint4(u[8], u[9], u[10], u[11]);
}

__global__ __launch_bounds__(256, 2)
void conv_mma_kernel(const float* __restrict__ x, const float* __restrict__ w,
                     const float* __restrict__ bias, float* __restrict__ out)
{
    const int tid  = threadIdx.x;
    const int warp = tid >> 5;
    const int lane = tid & 31;
    const int g    = lane >> 2;       // fragment group
    const int q    = lane & 3;        // thread-in-group
    const int nh   = warp & 1;        // n-half: couts [nh*32, nh*32+32)
    const int mq   = warp >> 1;       // m-quarter: rows [mq*32, mq*32+32)

    const int strip = blockIdx.x;
    const int b     = blockIdx.y;
    const int oy0   = strip * STRIP_OROWS;
    const uint32_t sbase = smem_u32(smem);
    float* red = (float*)(smem + OFF_RED);

    // ---- B into smem, once: rows = cout n (K-major, 48 bf16, per-kh block) ----
    for (int idx = tid; idx < 3 * 64 * 48; idx += 256) {
        const int kh = idx / (64 * 48);
        const int rm = idx % (64 * 48);
        const int n  = rm / 48;
        const int k  = rm % 48;
        const float val = __ldg(w + n * 144 + (k / 3) * 9 + kh * 3 + (k % 3));
        *reinterpret_cast<__nv_bfloat16*>(smem + OFF_B + kh * BKH_BYTES
                                          + n * APITCH + k * 2) = __float2bfloat16(val);
    }

    // loop-invariant bias for this thread's C columns (8 regs)
    float blo[4], bhi[4];
    #pragma unroll
    for (int nt = 0; nt < 4; nt++) {
        blo[nt] = __ldg(bias + nh * 32 + nt * 8 + 2 * q);
        bhi[nt] = __ldg(bias + nh * 32 + nt * 8 + 2 * q + 1);
    }

    const float* xb = x + ((size_t)b << 20);

    // ldmatrix lane addresses
    const uint32_t a_row_off  = (uint32_t)((lane & 15) * APITCH + ((lane >> 4) << 4));
    const uint32_t b_lane_off = (uint32_t)((nh * 32 + ((lane >> 3) >> 1) * 8 + (lane & 7)) * APITCH
                                           + (((lane >> 3) & 1) << 4));

    // ---- prologue: A chunks 0..4 ----
    #pragma unroll 1
    for (int pc = 0; pc < 5; pc++) {
        float v[24];
        load_vals(pc, oy0, xb, tid, v);
        store_vals(pc, tid, v);
    }
    __syncthreads();

    // ---- main pipeline: ONE barrier per iteration ----
    #pragma unroll 1
    for (int i = 0; i < OCHUNKS; i++) {
        // stage next build's 24 LDGs now; latency hides behind the MMA block
        const int ch = i + 5;
        float v[24];
        if (ch < ICHUNKS) load_vals(ch, oy0, xb, tid, v);

        float acc[2][4][4];
        #pragma unroll
        for (int nt = 0; nt < 4; nt++) {
            #pragma unroll
            for (int mt = 0; mt < 2; mt++) {
                acc[mt][nt][0] = blo[nt]; acc[mt][nt][1] = bhi[nt];
                acc[mt][nt][2] = blo[nt]; acc[mt][nt][3] = bhi[nt];
            }
        }

        #pragma unroll
        for (int kh = 0; kh < 3; kh++) {
            const uint32_t slotbase = sbase + OFF_A
                                    + (uint32_t)(((i + 2 * kh) % NSLOTS) * SLOT_BYTES);
            const uint32_t bbase = sbase + OFF_B + kh * BKH_BYTES + b_lane_off;
            #pragma unroll
            for (int s = 0; s < 3; s++) {
                uint32_t bf[8];
                ldmatrix_x4(bf[0], bf[1], bf[2], bf[3], bbase + s * 32);
                ldmatrix_x4(bf[4], bf[5], bf[6], bf[7], bbase + 16 * APITCH + s * 32);
                #pragma unroll
                for (int mt = 0; mt < 2; mt++) {
                    uint32_t addr = slotbase + (uint32_t)((mq * 32 + mt * 16) * APITCH)
                                  + a_row_off + s * 32;
                    uint32_t a0, a1, a2, a3;
                    ldmatrix_x4(a0, a1, a2, a3, addr);
                    #pragma unroll
                    for (int nt = 0; nt < 4; nt++)
                        mma_bf16(acc[mt][nt], a0, a1, a2, a3,
                                 bf[nt * 2], bf[nt * 2 + 1]);
                }
            }
        }

        // ---- epilogue part 1: warp min -> ping-pong red buffer ----
        float m[4];
        #pragma unroll
        for (int mt = 0; mt < 2; mt++) {
            float lo = fminf(acc[mt][0][0], acc[mt][0][1]);
            float hi = fminf(acc[mt][0][2], acc[mt][0][3]);
            #pragma unroll
            for (int nt = 1; nt < 4; nt++) {
                lo = fminf(lo, fminf(acc[mt][nt][0], acc[mt][nt][1]));
                hi = fminf(hi, fminf(acc[mt][nt][2], acc[mt][nt][3]));
            }
            m[mt * 2]     = lo;   // row mq*32 + mt*16 + g
            m[mt * 2 + 1] = hi;   // row mq*32 + mt*16 + g + 8
        }
        #pragma unroll
        for (int j = 0; j < 4; j++) {
            m[j] = fminf(m[j], __shfl_xor_sync(0xFFFFFFFFu, m[j], 1));
            m[j] = fminf(m[j], __shfl_xor_sync(0xFFFFFFFFu, m[j], 2));
        }
        float* redp = red + (i & 1) * 256;
        if (q == 0) {
            const int rb = mq * 32 + g;
            redp[(rb     ) * 2 + nh] = m[0];
            redp[(rb +  8) * 2 + nh] = m[1];
            redp[(rb + 16) * 2 + nh] = m[2];
            redp[(rb + 24) * 2 + nh] = m[3];
        }

        // commit the staged build (cvt + STS), then the single barrier
        if (ch < ICHUNKS) store_vals(ch, tid, v);
        __syncthreads();

        // ---- epilogue part 2: combine halves, tanh(tanh), store ----
        if (tid < 128) {
            float mm = fminf(redp[2 * tid], redp[2 * tid + 1]);
            float y  = tanhf(tanhf(mm));
            const int p  = i * 128 + tid;
            const int oy = oy0 + (p >> 8);
            const int ox = p & 255;
            if (ox < OHW && oy < OHW)
                out[((size_t)b * OHW + oy) * OHW + ox] = y;
        }
        // ordering: part-2 reads red[i&1]; next write to that buffer is in
        // iteration i+2, after sync(i+1). Ring slot i%6 is rewritten by
        // build(i+6) in iteration i+1, after sync(i) — ordered vs compute(i).
    }
}

extern "C" void kernel_launch(void* const* d_in, const int* in_sizes, int n_in,
                              void* d_out, int out_size)
{
    const float* x    = (const float*)d_in[0];   // [64,16,256,256]
    const float* w    = (const float*)d_in[1];   // [64,16,3,3]
    const float* bias = (const float*)d_in[2];   // [64]
    float* out = (float*)d_out;                  // [64,1,254,254]

    cudaFuncSetAttribute(conv_mma_kernel,
                         cudaFuncAttributeMaxDynamicSharedMemorySize, SMEM_BYTES);

    dim3 grid(STRIPS, 64);   // 16 strips x 64 images = 1024 CTAs
    conv_mma_kernel<<<grid, 256, SMEM_BYTES>>>(x, w, bias, out);
}

// round 10
// speedup vs baseline: 1.3420x; 1.0963x over previous
#include <cuda_runtime.h>
#include <cuda_bf16.h>
#include <math.h>
#include <stdint.h>

// ---------------- problem constants ----------------
#define OHW         254
#define STRIP_OROWS 16
#define STRIPS      16
#define ITERS       16          // 256 output pixels per iteration
#define NCHUNKS     36          // buildable 128-row input chunks per strip
#define RING_MASK   1023        // 8-chunk ring (1024 rows)
#define PITCH       48          // bytes per A/B row (32 data + 16 pad; conflict-free)
#define OFF_RED     0           // 2 x 512 floats (ping-pong)
#define OFF_B       4096        // 9 tiles x 64 rows x 48B = 27648
#define OFF_A       (4096 + 27648)              // 31744
#define SMEM_BYTES  (OFF_A + 1024 * PITCH)      // 80896 (x2 CTAs = 161792)

__device__ __forceinline__ uint32_t smem_u32(const void* p) {
    uint32_t a;
    asm("{ .reg .u64 t; cvta.to.shared.u64 t, %1; cvt.u32.u64 %0, t; }"
        : "=r"(a) : "l"(p));
    return a;
}
__device__ __forceinline__ void ldmatrix_x4(uint32_t& a0, uint32_t& a1,
                                            uint32_t& a2, uint32_t& a3,
                                            uint32_t addr) {
    asm volatile("ldmatrix.sync.aligned.m8n8.x4.shared.b16 {%0,%1,%2,%3}, [%4];"
                 : "=r"(a0), "=r"(a1), "=r"(a2), "=r"(a3) : "r"(addr));
}
__device__ __forceinline__ void mma_bf16(float* c, uint32_t a0, uint32_t a1,
                                         uint32_t a2, uint32_t a3,
                                         uint32_t b0, uint32_t b1) {
    asm volatile(
        "mma.sync.aligned.m16n8k16.row.col.f32.bf16.bf16.f32 "
        "{%0,%1,%2,%3}, {%4,%5,%6,%7}, {%8,%9}, {%0,%1,%2,%3};"
        : "+f"(c[0]), "+f"(c[1]), "+f"(c[2]), "+f"(c[3])
        : "r"(a0), "r"(a1), "r"(a2), "r"(a3), "r"(b0), "r"(b1));
}
__device__ __forceinline__ uint32_t pkbf(float lo, float hi) {
    __nv_bfloat162 t = __float22bfloat162_rn(make_float2(lo, hi));
    return *reinterpret_cast<uint32_t*>(&t);
}

extern __shared__ char smem[];

// Load 16 channel values for one input pixel row (256 threads cover 2 chunks).
__device__ __forceinline__ void load16(int c0, int oy0,
                                       const float* __restrict__ xb,
                                       int tid, float* v) {
    const int p  = c0 * 128 + tid;
    const int iy = oy0 + (p >> 8);
    const int ix = p & 255;
    if (iy < 256) {
        const float* xp = xb + iy * 256 + ix;
        #pragma unroll
        for (int ci = 0; ci < 16; ci++) v[ci] = __ldg(xp + (ci << 16));
    } else {
        #pragma unroll
        for (int ci = 0; ci < 16; ci++) v[ci] = 0.0f;
    }
}
// Convert + store one staged pixel row into the ring (row index mod 1024).
__device__ __forceinline__ void store16(int c0, int tid, const float* v) {
    const int rp = (c0 * 128 + tid) & RING_MASK;
    uint32_t u[8];
    #pragma unroll
    for (int j = 0; j < 8; j++) u[j] = pkbf(v[2 * j], v[2 * j + 1]);
    char* base = smem + OFF_A + rp * PITCH;
    *reinterpret_cast<uint4*>(base)      = make_uint4(u[0], u[1], u[2], u[3]);
    *reinterpret_cast<uint4*>(base + 16) = make_uint4(u[4], u[5], u[6], u[7]);
}

__global__ __launch_bounds__(256, 2)
void conv_mma_kernel(const float* __restrict__ x, const float* __restrict__ w,
                     const float* __restrict__ bias, float* __restrict__ out)
{
    const int tid  = threadIdx.x;
    const int warp = tid >> 5;
    const int lane = tid & 31;
    const int g    = lane >> 2;       // fragment group (row / n index)
    const int q    = lane & 3;        // thread-in-group
    const int nh   = warp & 1;        // n-half: couts [nh*32, nh*32+32)
    const int mq   = warp >> 1;       // m-quarter: rows [mq*64, mq*64+64) of 256

    const int strip = blockIdx.x;
    const int b     = blockIdx.y;
    const int oy0   = strip * STRIP_OROWS;
    const uint32_t sbase = smem_u32(smem);
    float* red = (float*)(smem + OFF_RED);

    // ---- B: 9 tiles (kh*3+kw), rows = cout n, 16 ci bf16 per row ----
    // B[t][n][ci] = w[n*144 + ci*9 + t]
    for (int idx = tid; idx < 9 * 64 * 16; idx += 256) {
        const int t  = idx >> 10;
        const int rm = idx & 1023;
        const int n  = rm >> 4;
        const int ci = rm & 15;
        const float val = __ldg(w + n * 144 + ci * 9 + t);
        *reinterpret_cast<__nv_bfloat16*>(smem + OFF_B + t * (64 * PITCH)
                                          + n * PITCH + ci * 2) = __float2bfloat16(val);
    }

    // loop-invariant bias for this thread's C columns (8 regs)
    float blo[4], bhi[4];
    #pragma unroll
    for (int nt = 0; nt < 4; nt++) {
        blo[nt] = __ldg(bias + nh * 32 + nt * 8 + 2 * q);
        bhi[nt] = __ldg(bias + nh * 32 + nt * 8 + 2 * q + 1);
    }

    const float* xb = x + ((size_t)b << 20);

    // lane-constant pieces of ldmatrix addresses
    const int      a_lane_row = lane & 15;
    const uint32_t a_col_off  = (uint32_t)((lane >> 4) << 4);
    const uint32_t b_lane_off = (uint32_t)((((lane >> 3) >> 1) * 8 + (lane & 7)) * PITCH
                                           + (((lane >> 3) & 1) << 4));
    const uint32_t b_base = sbase + OFF_B + (uint32_t)(nh * 32 * PITCH) + b_lane_off;
    const uint32_t a_base = sbase + OFF_A;

    // ---- prologue: chunks 0..7 (fill the whole ring) ----
    #pragma unroll 1
    for (int j = 0; j < 4; j++) {
        float v[16];
        load16(2 * j, oy0, xb, tid, v);
        store16(2 * j, tid, v);
    }
    __syncthreads();

    // ---- main pipeline ----
    #pragma unroll 1
    for (int i = 0; i < ITERS; i++) {
        // stage next build's 16 LDGs (chunks 2i+8, 2i+9); hides behind MMAs
        const int c0 = 2 * i + 8;
        float v[16];
        if (c0 < NCHUNKS) load16(c0, oy0, xb, tid, v);

        float acc[4][4][4];
        #pragma unroll
        for (int mt = 0; mt < 4; mt++)
            #pragma unroll
            for (int nt = 0; nt < 4; nt++) {
                acc[mt][nt][0] = blo[nt]; acc[mt][nt][1] = bhi[nt];
                acc[mt][nt][2] = blo[nt]; acc[mt][nt][3] = bhi[nt];
            }

        // 9 shift-steps: sh = kh*256 + kw
        const int prow = i * 256 + mq * 64 + a_lane_row;
        #pragma unroll
        for (int kh = 0; kh < 3; kh++) {
            #pragma unroll
            for (int kw = 0; kw < 3; kw++) {
                const int step = kh * 3 + kw;
                // B fragments for 4 n-tiles (reused across 4 m-tiles)
                uint32_t bf[8];
                const uint32_t bt = b_base + (uint32_t)(step * 64 * PITCH);
                ldmatrix_x4(bf[0], bf[1], bf[2], bf[3], bt);
                ldmatrix_x4(bf[4], bf[5], bf[6], bf[7], bt + 16 * PITCH);
                const int p0 = prow + kh * 256 + kw;
                #pragma unroll
                for (int mt = 0; mt < 4; mt++) {
                    const uint32_t addr = a_base
                        + (uint32_t)(((p0 + mt * 16) & RING_MASK) * PITCH) + a_col_off;
                    uint32_t a0, a1, a2, a3;
                    ldmatrix_x4(a0, a1, a2, a3, addr);
                    #pragma unroll
                    for (int nt = 0; nt < 4; nt++)
                        mma_bf16(acc[mt][nt], a0, a1, a2, a3,
                                 bf[nt * 2], bf[nt * 2 + 1]);
                }
            }
        }

        // ---- epilogue part 1: min over this warp's 32 couts -> red ----
        float m[8];
        #pragma unroll
        for (int mt = 0; mt < 4; mt++) {
            float lo = fminf(acc[mt][0][0], acc[mt][0][1]);
            float hi = fminf(acc[mt][0][2], acc[mt][0][3]);
            #pragma unroll
            for (int nt = 1; nt < 4; nt++) {
                lo = fminf(lo, fminf(acc[mt][nt][0], acc[mt][nt][1]));
                hi = fminf(hi, fminf(acc[mt][nt][2], acc[mt][nt][3]));
            }
            m[2 * mt]     = lo;   // row mq*64 + mt*16 + g
            m[2 * mt + 1] = hi;   // row mq*64 + mt*16 + g + 8
        }
        #pragma unroll
        for (int j = 0; j < 8; j++) {
            m[j] = fminf(m[j], __shfl_xor_sync(0xFFFFFFFFu, m[j], 1));
            m[j] = fminf(m[j], __shfl_xor_sync(0xFFFFFFFFu, m[j], 2));
        }
        float* redp = red + (i & 1) * 512;
        if (q == 0) {
            const int rb = mq * 64 + g;
            #pragma unroll
            for (int j = 0; j < 8; j++)
                redp[(rb + j * 8) * 2 + nh] = m[j];
        }

        // barrier 1: all MMA reads of ring done; red(i) visible
        __syncthreads();

        // commit staged build (overwrites ring slots 2i,2i+1 — now safe)
        if (c0 < NCHUNKS) store16(c0, tid, v);

        // ---- epilogue part 2: combine halves, tanh(tanh), store ----
        {
            float mm = fminf(redp[2 * tid], redp[2 * tid + 1]);
            float y  = tanhf(tanhf(mm));
            const int p  = i * 256 + tid;
            const int oy = oy0 + (p >> 8);
            const int ox = p & 255;
            if (ox < OHW && oy < OHW)
                out[((size_t)b * OHW + oy) * OHW + ox] = y;
        }

        // barrier 2: STS visible before compute(i+1); red reuse spaced 2 iters
        __syncthreads();
    }
}

extern "C" void kernel_launch(void* const* d_in, const int* in_sizes, int n_in,
                              void* d_out, int out_size)
{
    const float* x    = (const float*)d_in[0];   // [64,16,256,256]
    const float* w    = (const float*)d_in[1];   // [64,16,3,3]
    const float* bias = (const float*)d_in[2];   // [64]
    float* out = (float*)d_out;                  // [64,1,254,254]

    cudaFuncSetAttribute(conv_mma_kernel,
                         cudaFuncAttributeMaxDynamicSharedMemorySize, SMEM_BYTES);

    dim3 grid(STRIPS, 64);   // 16 strips x 64 images = 1024 CTAs
    conv_mma_kernel<<<grid, 256, SMEM_BYTES>>>(x, w, bias, out);
}

// round 11
// speedup vs baseline: 1.3427x; 1.0005x over previous
#include <cuda_runtime.h>
#include <cuda_bf16.h>
#include <math.h>
#include <stdint.h>

// ---------------- problem constants ----------------
#define OHW         254
#define STRIP_OROWS 16
#define STRIPS      16
#define ITERS       16          // 256 output pixels per iteration
#define NCHUNKS     36          // buildable 128-row input chunks per strip
#define RING_ROWS   1280        // 10-chunk ring
#define PITCH       48          // bytes per A/B row (32 data + 16 pad; conflict-free)
#define OFF_RED     0           // 2 x 512 floats (ping-pong)
#define OFF_B       4096        // 9 tiles x 64 rows x 48B = 27648
#define OFF_A       (4096 + 27648)                  // 31744
#define SMEM_BYTES  (OFF_A + RING_ROWS * PITCH)     // 93184 (x2 CTAs = 186368)

__device__ __forceinline__ uint32_t smem_u32(const void* p) {
    uint32_t a;
    asm("{ .reg .u64 t; cvta.to.shared.u64 t, %1; cvt.u32.u64 %0, t; }"
        : "=r"(a) : "l"(p));
    return a;
}
__device__ __forceinline__ void ldmatrix_x4(uint32_t& a0, uint32_t& a1,
                                            uint32_t& a2, uint32_t& a3,
                                            uint32_t addr) {
    asm volatile("ldmatrix.sync.aligned.m8n8.x4.shared.b16 {%0,%1,%2,%3}, [%4];"
                 : "=r"(a0), "=r"(a1), "=r"(a2), "=r"(a3) : "r"(addr));
}
__device__ __forceinline__ void mma_bf16(float* c, uint32_t a0, uint32_t a1,
                                         uint32_t a2, uint32_t a3,
                                         uint32_t b0, uint32_t b1) {
    asm volatile(
        "mma.sync.aligned.m16n8k16.row.col.f32.bf16.bf16.f32 "
        "{%0,%1,%2,%3}, {%4,%5,%6,%7}, {%8,%9}, {%0,%1,%2,%3};"
        : "+f"(c[0]), "+f"(c[1]), "+f"(c[2]), "+f"(c[3])
        : "r"(a0), "r"(a1), "r"(a2), "r"(a3), "r"(b0), "r"(b1));
}
__device__ __forceinline__ uint32_t pkbf(float lo, float hi) {
    __nv_bfloat162 t = __float22bfloat162_rn(make_float2(lo, hi));
    return *reinterpret_cast<uint32_t*>(&t);
}

extern __shared__ char smem[];

// Load 16 channel values for one input pixel row (256 threads = 2 chunks).
__device__ __forceinline__ void load16(int c0, int oy0,
                                       const float* __restrict__ xb,
                                       int tid, float* v) {
    const int p  = c0 * 128 + tid;
    const int iy = oy0 + (p >> 8);
    const int ix = p & 255;
    if (iy < 256) {
        const float* xp = xb + iy * 256 + ix;
        #pragma unroll
        for (int ci = 0; ci < 16; ci++) v[ci] = __ldg(xp + (ci << 16));
    } else {
        #pragma unroll
        for (int ci = 0; ci < 16; ci++) v[ci] = 0.0f;
    }
}
// Convert + store one staged pixel row at a pre-wrapped ring row.
__device__ __forceinline__ void store16_at(int ring_row, const float* v) {
    uint32_t u[8];
    #pragma unroll
    for (int j = 0; j < 8; j++) u[j] = pkbf(v[2 * j], v[2 * j + 1]);
    char* base = smem + OFF_A + ring_row * PITCH;
    *reinterpret_cast<uint4*>(base)      = make_uint4(u[0], u[1], u[2], u[3]);
    *reinterpret_cast<uint4*>(base + 16) = make_uint4(u[4], u[5], u[6], u[7]);
}

__global__ __launch_bounds__(256, 2)
void conv_mma_kernel(const float* __restrict__ x, const float* __restrict__ w,
                     const float* __restrict__ bias, float* __restrict__ out)
{
    const int tid  = threadIdx.x;
    const int warp = tid >> 5;
    const int lane = tid & 31;
    const int g    = lane >> 2;       // fragment group (row / n index)
    const int q    = lane & 3;        // thread-in-group
    const int nh   = warp & 1;        // n-half: couts [nh*32, nh*32+32)
    const int mq   = warp >> 1;       // m-quarter: rows [mq*64, mq*64+64) of 256

    const int strip = blockIdx.x;
    const int b     = blockIdx.y;
    const int oy0   = strip * STRIP_OROWS;
    const uint32_t sbase = smem_u32(smem);
    float* red = (float*)(smem + OFF_RED);

    // ---- B: 9 tiles (kh*3+kw), rows = cout n, 16 ci bf16 per row ----
    for (int idx = tid; idx < 9 * 64 * 16; idx += 256) {
        const int t  = idx >> 10;
        const int rm = idx & 1023;
        const int n  = rm >> 4;
        const int ci = rm & 15;
        const float val = __ldg(w + n * 144 + ci * 9 + t);
        *reinterpret_cast<__nv_bfloat16*>(smem + OFF_B + t * (64 * PITCH)
                                          + n * PITCH + ci * 2) = __float2bfloat16(val);
    }

    // loop-invariant bias (8 regs)
    float blo[4], bhi[4];
    #pragma unroll
    for (int nt = 0; nt < 4; nt++) {
        blo[nt] = __ldg(bias + nh * 32 + nt * 8 + 2 * q);
        bhi[nt] = __ldg(bias + nh * 32 + nt * 8 + 2 * q + 1);
    }

    const float* xb = x + ((size_t)b << 20);

    // lane-constant pieces of ldmatrix addresses
    const uint32_t a_col_off  = (uint32_t)((lane >> 4) << 4);
    const uint32_t b_lane_off = (uint32_t)((((lane >> 3) >> 1) * 8 + (lane & 7)) * PITCH
                                           + (((lane >> 3) & 1) << 4));
    const uint32_t b_base = sbase + OFF_B + (uint32_t)(nh * 32 * PITCH) + b_lane_off;
    const uint32_t a_base = sbase + OFF_A;

    // ---- prologue: chunks 0..7 (rows 0..1023, no wrap) ----
    #pragma unroll 1
    for (int j = 0; j < 4; j++) {
        float v[16];
        load16(2 * j, oy0, xb, tid, v);
        store16_at(2 * j * 128 + tid, v);
    }
    __syncthreads();

    // incremental ring bases (both already in [0, RING_ROWS))
    int sts_row = 1024 + tid;                 // ring row of chunk-8 + tid
    int a_row0  = mq * 64 + (lane & 15);      // warp's M base for i=0

    // ---- main pipeline: ONE barrier per iteration ----
    #pragma unroll 1
    for (int i = 0; i < ITERS; i++) {
        // deferred epilogue part 2 of iteration i-1 (overlaps with this MMA block)
        if (i > 0) {
            const float* redp = red + ((i - 1) & 1) * 512;
            float mm = fminf(redp[2 * tid], redp[2 * tid + 1]);
            float y  = tanhf(tanhf(mm));
            const int p  = (i - 1) * 256 + tid;
            const int oy = oy0 + (p >> 8);
            const int ox = p & 255;
            if (ox < OHW && oy < OHW)
                out[((size_t)b * OHW + oy) * OHW + ox] = y;
        }

        // stage next build's 16 LDGs (chunks 2i+8, 2i+9)
        const int c0 = 2 * i + 8;
        float v[16];
        if (c0 < NCHUNKS) load16(c0, oy0, xb, tid, v);

        float acc[4][4][4];
        #pragma unroll
        for (int mt = 0; mt < 4; mt++)
            #pragma unroll
            for (int nt = 0; nt < 4; nt++) {
                acc[mt][nt][0] = blo[nt]; acc[mt][nt][1] = bhi[nt];
                acc[mt][nt][2] = blo[nt]; acc[mt][nt][3] = bhi[nt];
            }

        // 9 shift-steps over the ring (reads chunks 2i..2i+6)
        #pragma unroll
        for (int kh = 0; kh < 3; kh++) {
            int rk = a_row0 + kh * 256;
            if (rk >= RING_ROWS) rk -= RING_ROWS;
            #pragma unroll
            for (int kw = 0; kw < 3; kw++) {
                const int step = kh * 3 + kw;
                uint32_t bf[8];
                const uint32_t bt = b_base + (uint32_t)(step * 64 * PITCH);
                ldmatrix_x4(bf[0], bf[1], bf[2], bf[3], bt);
                ldmatrix_x4(bf[4], bf[5], bf[6], bf[7], bt + 16 * PITCH);
                #pragma unroll
                for (int mt = 0; mt < 4; mt++) {
                    int row = rk + kw + mt * 16;
                    if (row >= RING_ROWS) row -= RING_ROWS;
                    uint32_t a0, a1, a2, a3;
                    ldmatrix_x4(a0, a1, a2, a3,
                                a_base + (uint32_t)(row * PITCH) + a_col_off);
                    #pragma unroll
                    for (int nt = 0; nt < 4; nt++)
                        mma_bf16(acc[mt][nt], a0, a1, a2, a3,
                                 bf[nt * 2], bf[nt * 2 + 1]);
                }
            }
        }

        // ---- epilogue part 1: min over this warp's 32 couts -> red[i&1] ----
        float m[8];
        #pragma unroll
        for (int mt = 0; mt < 4; mt++) {
            float lo = fminf(acc[mt][0][0], acc[mt][0][1]);
            float hi = fminf(acc[mt][0][2], acc[mt][0][3]);
            #pragma unroll
            for (int nt = 1; nt < 4; nt++) {
                lo = fminf(lo, fminf(acc[mt][nt][0], acc[mt][nt][1]));
                hi = fminf(hi, fminf(acc[mt][nt][2], acc[mt][nt][3]));
            }
            m[2 * mt]     = lo;   // row mq*64 + mt*16 + g
            m[2 * mt + 1] = hi;   // row mq*64 + mt*16 + g + 8
        }
        #pragma unroll
        for (int j = 0; j < 8; j++) {
            m[j] = fminf(m[j], __shfl_xor_sync(0xFFFFFFFFu, m[j], 1));
            m[j] = fminf(m[j], __shfl_xor_sync(0xFFFFFFFFu, m[j], 2));
        }
        float* redp = red + (i & 1) * 512;
        if (q == 0) {
            const int rb = mq * 64 + g;
            #pragma unroll
            for (int j = 0; j < 8; j++)
                redp[(rb + j * 8) * 2 + nh] = m[j];
        }

        // commit staged build — target slots (chunks 2i+8,2i+9) are DISJOINT
        // from the read window (2i..2i+6) in the 10-chunk ring: no barrier needed
        if (c0 < NCHUNKS) store16_at(sts_row, v);

        // single barrier: orders STS(i)->reads(i+1), red writes->part2 reads,
        // and part2(i-1) reads -> red rewrite in i+1
        __syncthreads();

        a_row0 += 256; if (a_row0 >= RING_ROWS) a_row0 -= RING_ROWS;
        sts_row += 256; if (sts_row >= RING_ROWS) sts_row -= RING_ROWS;
    }

    // final deferred epilogue (iteration ITERS-1)
    {
        const float* redp = red + ((ITERS - 1) & 1) * 512;
        float mm = fminf(redp[2 * tid], redp[2 * tid + 1]);
        float y  = tanhf(tanhf(mm));
        const int p  = (ITERS - 1) * 256 + tid;
        const int oy = oy0 + (p >> 8);
        const int ox = p & 255;
        if (ox < OHW && oy < OHW)
            out[((size_t)b * OHW + oy) * OHW + ox] = y;
    }
}

extern "C" void kernel_launch(void* const* d_in, const int* in_sizes, int n_in,
                              void* d_out, int out_size)
{
    const float* x    = (const float*)d_in[0];   // [64,16,256,256]
    const float* w    = (const float*)d_in[1];   // [64,16,3,3]
    const float* bias = (const float*)d_in[2];   // [64]
    float* out = (float*)d_out;                  // [64,1,254,254]

    cudaFuncSetAttribute(conv_mma_kernel,
                         cudaFuncAttributeMaxDynamicSharedMemorySize, SMEM_BYTES);

    dim3 grid(STRIPS, 64);   // 16 strips x 64 images = 1024 CTAs
    conv_mma_kernel<<<grid, 256, SMEM_BYTES>>>(x, w, bias, out);
}